// round 3
// baseline (speedup 1.0000x reference)
#include <cuda_runtime.h>
#include <cuda_bf16.h>
#include <math_constants.h>
#include <cstdint>

#define BATCH 2
#define SEQ   2048
#define EMB   1024
#define HEADS 16
#define HDIM  64
#define ROWS  (BATCH * SEQ)   // 4096

// Scratch (allocation-free rule: __device__ globals)
__device__ float g_Q[ROWS * EMB];
__device__ float g_K[ROWS * HDIM];
__device__ float g_V[ROWS * HDIM];

// ---------------------------------------------------------------------------
// Helpers
// ---------------------------------------------------------------------------
__device__ __forceinline__ uint32_t f2tf32(float x) {
    uint32_t u;
    asm("cvt.rna.tf32.f32 %0, %1;" : "=r"(u) : "f"(x));
    return u;
}

#define CP_ASYNC16(saddr, gptr) \
    asm volatile("cp.async.cg.shared.global [%0], [%1], 16;" \
                 :: "r"(saddr), "l"(gptr))
#define CP_COMMIT() asm volatile("cp.async.commit_group;" ::: "memory")
#define CP_WAIT(n)  asm volatile("cp.async.wait_group %0;" :: "n"(n) : "memory")

__device__ __forceinline__ void mma_tf32(float c[4], const uint32_t a[4],
                                         const uint32_t b[2]) {
    asm volatile(
        "mma.sync.aligned.m16n8k8.row.col.f32.tf32.tf32.f32 "
        "{%0,%1,%2,%3}, {%4,%5,%6,%7}, {%8,%9}, {%0,%1,%2,%3};"
        : "+f"(c[0]), "+f"(c[1]), "+f"(c[2]), "+f"(c[3])
        : "r"(a[0]), "r"(a[1]), "r"(a[2]), "r"(a[3]), "r"(b[0]), "r"(b[1]));
}

// ---------------------------------------------------------------------------
// Projection GEMM: C[M,N] = A[M,K] @ W[K,N], row-major, tf32 mma.sync.
// CTA tile 128 x CTA_N, BK=16, cp.async double buffer, 8 warps (2m x 4n),
// warp tile 64 x (8*WNT). M,K multiples of 128/16; N multiple of CTA_N.
// ---------------------------------------------------------------------------
template <int CTA_N, int WNT>
__global__ __launch_bounds__(256) void proj_mma(
    const float* __restrict__ A, const float* __restrict__ Bg,
    float* __restrict__ C, int M, int N, int K)
{
    __shared__ float As[2][128][20];           // [m][k] pad 20
    __shared__ float Bs[2][16][CTA_N + 4];     // [k][n] pad +4

    const int tid  = threadIdx.x;
    const int lane = tid & 31;
    const int wid  = tid >> 5;
    const int wm   = wid >> 2;          // 0..1
    const int wn   = wid & 3;           // 0..3
    const int tr   = lane >> 2;         // 0..7
    const int tc   = lane & 3;          // 0..3
    const int m0   = blockIdx.y * 128;
    const int n0   = blockIdx.x * CTA_N;

    float acc[4][WNT][4];
#pragma unroll
    for (int mt = 0; mt < 4; mt++)
#pragma unroll
        for (int nt = 0; nt < WNT; nt++)
#pragma unroll
            for (int q = 0; q < 4; q++) acc[mt][nt][q] = 0.0f;

    const int nch = K / 16;

    // tile loader (global -> smem via cp.async)
    auto load_tile = [&](int c) {
        const int buf = c & 1;
        const int k0 = c * 16;
        // A: 128 rows x 4 quads
#pragma unroll
        for (int i = tid; i < 512; i += 256) {
            int r = i >> 2, q = i & 3;
            uint32_t s = (uint32_t)__cvta_generic_to_shared(&As[buf][r][q * 4]);
            CP_ASYNC16(s, A + (size_t)(m0 + r) * K + k0 + q * 4);
        }
        // B: 16 rows x CTA_N/4 quads
#pragma unroll
        for (int i = tid; i < 16 * (CTA_N / 4); i += 256) {
            int r = i / (CTA_N / 4), q = i % (CTA_N / 4);
            uint32_t s = (uint32_t)__cvta_generic_to_shared(&Bs[buf][r][q * 4]);
            CP_ASYNC16(s, Bg + (size_t)(k0 + r) * N + n0 + q * 4);
        }
    };

    load_tile(0);
    CP_COMMIT();

    for (int c = 0; c < nch; c++) {
        if (c + 1 < nch) {
            load_tile(c + 1);
            CP_COMMIT();
            CP_WAIT(1);
        } else {
            CP_WAIT(0);
        }
        __syncthreads();

        const int buf = c & 1;
#pragma unroll
        for (int ks = 0; ks < 16; ks += 8) {
            uint32_t af[4][4];
#pragma unroll
            for (int mt = 0; mt < 4; mt++) {
                int r = wm * 64 + mt * 16 + tr;
                af[mt][0] = f2tf32(As[buf][r][ks + tc]);
                af[mt][1] = f2tf32(As[buf][r + 8][ks + tc]);
                af[mt][2] = f2tf32(As[buf][r][ks + tc + 4]);
                af[mt][3] = f2tf32(As[buf][r + 8][ks + tc + 4]);
            }
            uint32_t bf[WNT][2];
#pragma unroll
            for (int nt = 0; nt < WNT; nt++) {
                int col = wn * (8 * WNT) + nt * 8 + tr;
                bf[nt][0] = f2tf32(Bs[buf][ks + tc][col]);
                bf[nt][1] = f2tf32(Bs[buf][ks + tc + 4][col]);
            }
#pragma unroll
            for (int mt = 0; mt < 4; mt++)
#pragma unroll
                for (int nt = 0; nt < WNT; nt++)
                    mma_tf32(acc[mt][nt], af[mt], bf[nt]);
        }
        __syncthreads();
    }

    // Epilogue: direct vectorized global stores
#pragma unroll
    for (int mt = 0; mt < 4; mt++) {
        int r0 = m0 + wm * 64 + mt * 16 + tr;
#pragma unroll
        for (int nt = 0; nt < WNT; nt++) {
            int col = n0 + wn * (8 * WNT) + nt * 8 + 2 * tc;
            *(float2*)(C + (size_t)r0 * N + col) =
                make_float2(acc[mt][nt][0], acc[mt][nt][1]);
            *(float2*)(C + (size_t)(r0 + 8) * N + col) =
                make_float2(acc[mt][nt][2], acc[mt][nt][3]);
        }
    }
}

// ---------------------------------------------------------------------------
// Flash attention (causal, MQA). 64x64 tiles, 256 threads (16x16), 4x4/thread.
// All smem traffic via LDS.128/STS.128 (row pad = 68 floats for 16B alignment).
// ---------------------------------------------------------------------------
#define SPAD 68
#define QT 64
#define FLASH_SMEM (4 * 64 * SPAD * 4)

extern __shared__ float fsm[];

__global__ __launch_bounds__(256) void flash_mqa(
    const float* __restrict__ Qg, const float* __restrict__ Kg,
    const float* __restrict__ Vg, float* __restrict__ out)
{
    float* Qs = fsm;                   // [d][row]   (transposed, pre-scaled)
    float* Ks = fsm + 64 * SPAD;       // [d][key]   (transposed)
    float* Vs = fsm + 2 * 64 * SPAD;   // [key][d]
    float* Ps = fsm + 3 * 64 * SPAD;   // [key][row] (transposed)

    const int tid = threadIdx.x;
    const int tx = tid & 15;
    const int ty = tid >> 4;
    const int q0 = blockIdx.x * QT;
    const int h  = blockIdx.y;
    const int b  = blockIdx.z;
    const float scale = 0.125f;

    for (int e = tid; e < 64 * 16; e += 256) {
        int r = e >> 4, dq = e & 15;
        float4 v = *(const float4*)(Qg + (size_t)(b * SEQ + q0 + r) * EMB + h * HDIM + dq * 4);
        int d = dq * 4;
        Qs[(d + 0) * SPAD + r] = v.x * scale;
        Qs[(d + 1) * SPAD + r] = v.y * scale;
        Qs[(d + 2) * SPAD + r] = v.z * scale;
        Qs[(d + 3) * SPAD + r] = v.w * scale;
    }

    float m[4], l[4], o[4][4];
#pragma unroll
    for (int i = 0; i < 4; i++) {
        m[i] = -CUDART_INF_F;
        l[i] = 0.0f;
#pragma unroll
        for (int j = 0; j < 4; j++) o[i][j] = 0.0f;
    }

    const int ktm = q0 / 64;
    for (int kt = 0; kt <= ktm; kt++) {
        __syncthreads();
        const int k0 = kt * 64;
        for (int e = tid; e < 64 * 16; e += 256) {
            int r = e >> 4, dq = e & 15;
            float4 kv = *(const float4*)(Kg + (size_t)(b * SEQ + k0 + r) * HDIM + dq * 4);
            float4 vv = *(const float4*)(Vg + (size_t)(b * SEQ + k0 + r) * HDIM + dq * 4);
            int d = dq * 4;
            Ks[(d + 0) * SPAD + r] = kv.x;
            Ks[(d + 1) * SPAD + r] = kv.y;
            Ks[(d + 2) * SPAD + r] = kv.z;
            Ks[(d + 3) * SPAD + r] = kv.w;
            *(float4*)(Vs + r * SPAD + d) = vv;
        }
        __syncthreads();

        float s[4][4];
#pragma unroll
        for (int i = 0; i < 4; i++)
#pragma unroll
            for (int j = 0; j < 4; j++) s[i][j] = 0.0f;

#pragma unroll 8
        for (int d = 0; d < 64; d++) {
            float4 a4 = *(const float4*)(Qs + d * SPAD + ty * 4);
            float4 k4 = *(const float4*)(Ks + d * SPAD + tx * 4);
            float a[4] = {a4.x, a4.y, a4.z, a4.w};
            float kk[4] = {k4.x, k4.y, k4.z, k4.w};
#pragma unroll
            for (int i = 0; i < 4; i++)
#pragma unroll
                for (int j = 0; j < 4; j++) s[i][j] = fmaf(a[i], kk[j], s[i][j]);
        }

        if (kt == ktm) {
#pragma unroll
            for (int i = 0; i < 4; i++) {
                int q = q0 + ty * 4 + i;
#pragma unroll
                for (int j = 0; j < 4; j++)
                    if (k0 + tx * 4 + j > q) s[i][j] = -CUDART_INF_F;
            }
        }

        float mloc[4];
#pragma unroll
        for (int i = 0; i < 4; i++)
            mloc[i] = fmaxf(fmaxf(s[i][0], s[i][1]), fmaxf(s[i][2], s[i][3]));
#pragma unroll
        for (int off = 8; off >= 1; off >>= 1)
#pragma unroll
            for (int i = 0; i < 4; i++)
                mloc[i] = fmaxf(mloc[i], __shfl_xor_sync(0xffffffffu, mloc[i], off, 16));

        float mnew[4], corr[4];
#pragma unroll
        for (int i = 0; i < 4; i++) {
            mnew[i] = fmaxf(m[i], mloc[i]);
            corr[i] = __expf(m[i] - mnew[i]);
            m[i] = mnew[i];
        }

        float p[4][4], lloc[4];
#pragma unroll
        for (int i = 0; i < 4; i++) {
            lloc[i] = 0.0f;
#pragma unroll
            for (int j = 0; j < 4; j++) {
                p[i][j] = __expf(s[i][j] - mnew[i]);
                lloc[i] += p[i][j];
            }
        }
#pragma unroll
        for (int off = 8; off >= 1; off >>= 1)
#pragma unroll
            for (int i = 0; i < 4; i++)
                lloc[i] += __shfl_xor_sync(0xffffffffu, lloc[i], off, 16);
#pragma unroll
        for (int i = 0; i < 4; i++) {
            l[i] = l[i] * corr[i] + lloc[i];
#pragma unroll
            for (int j = 0; j < 4; j++) o[i][j] *= corr[i];
        }

        // Stage P transposed [key][row] so PV reads are LDS.128 on both sides
#pragma unroll
        for (int j = 0; j < 4; j++)
            *(float4*)(Ps + (tx * 4 + j) * SPAD + ty * 4) =
                make_float4(p[0][j], p[1][j], p[2][j], p[3][j]);
        __syncthreads();

#pragma unroll 8
        for (int j = 0; j < 64; j++) {
            float4 pp4 = *(const float4*)(Ps + j * SPAD + ty * 4);
            float4 vv4 = *(const float4*)(Vs + j * SPAD + tx * 4);
            float pp[4] = {pp4.x, pp4.y, pp4.z, pp4.w};
            float vv[4] = {vv4.x, vv4.y, vv4.z, vv4.w};
#pragma unroll
            for (int i = 0; i < 4; i++)
#pragma unroll
                for (int d = 0; d < 4; d++) o[i][d] = fmaf(pp[i], vv[d], o[i][d]);
        }
    }

#pragma unroll
    for (int i = 0; i < 4; i++) {
        float inv = 1.0f / l[i];
        int q = q0 + ty * 4 + i;
        float4* dst = (float4*)(out + (size_t)(b * SEQ + q) * EMB + h * HDIM + tx * 4);
        *dst = make_float4(o[i][0] * inv, o[i][1] * inv, o[i][2] * inv, o[i][3] * inv);
    }
}

// ---------------------------------------------------------------------------
// Launch
// ---------------------------------------------------------------------------
extern "C" void kernel_launch(void* const* d_in, const int* in_sizes, int n_in,
                              void* d_out, int out_size)
{
    const float* X  = (const float*)d_in[0];   // [B,S,E]
    const float* Wq = (const float*)d_in[1];   // [E,E]
    const float* Wk = (const float*)d_in[2];   // [E,D]
    const float* Wv = (const float*)d_in[3];   // [E,D]
    float* out = (float*)d_out;

    float *Qbuf, *Kbuf, *Vbuf;
    cudaGetSymbolAddress((void**)&Qbuf, g_Q);
    cudaGetSymbolAddress((void**)&Kbuf, g_K);
    cudaGetSymbolAddress((void**)&Vbuf, g_V);

    // Projections on mma.sync tf32
    {
        dim3 blk(256);
        dim3 gq(EMB / 128, ROWS / 128);   // (8, 32)
        proj_mma<128, 4><<<gq, blk>>>(X, Wq, Qbuf, ROWS, EMB, EMB);
        dim3 gk(1, ROWS / 128);           // (1, 32)
        proj_mma<64, 2><<<gk, blk>>>(X, Wk, Kbuf, ROWS, HDIM, EMB);
        proj_mma<64, 2><<<gk, blk>>>(X, Wv, Vbuf, ROWS, HDIM, EMB);
    }

    // Attention (vectorized SIMT flash)
    {
        cudaFuncSetAttribute(flash_mqa, cudaFuncAttributeMaxDynamicSharedMemorySize, FLASH_SMEM);
        dim3 blk(256);
        dim3 grid(SEQ / QT, HEADS, BATCH);   // (32, 16, 2)
        flash_mqa<<<grid, blk, FLASH_SMEM>>>(Qbuf, Kbuf, Vbuf, out);
    }
}

// round 5
// speedup vs baseline: 2.2437x; 2.2437x over previous
#include <cuda_runtime.h>
#include <cuda_bf16.h>
#include <math_constants.h>
#include <cstdint>

#define BATCH 2
#define SEQ   2048
#define EMB   1024
#define HEADS 16
#define HDIM  64
#define ROWS  (BATCH * SEQ)   // 4096

__device__ float g_Q[ROWS * EMB];
__device__ float g_K[ROWS * HDIM];
__device__ float g_V[ROWS * HDIM];

// ---------------------------------------------------------------------------
// Helpers
// ---------------------------------------------------------------------------
__device__ __forceinline__ uint32_t f2tf32(float x) {
    uint32_t u;
    asm("cvt.rna.tf32.f32 %0, %1;" : "=r"(u) : "f"(x));
    return u;
}

// Compensated split: x ~= hi + lo, both tf32-representable.
__device__ __forceinline__ void split_tf32(float x, uint32_t& h, uint32_t& l) {
    h = f2tf32(x);
    float r = x - __uint_as_float(h);
    l = f2tf32(r);
}

#define CP_ASYNC16(saddr, gptr) \
    asm volatile("cp.async.cg.shared.global [%0], [%1], 16;" \
                 :: "r"(saddr), "l"(gptr))
#define CP_COMMIT() asm volatile("cp.async.commit_group;" ::: "memory")
#define CP_WAIT(n)  asm volatile("cp.async.wait_group %0;" :: "n"(n) : "memory")

__device__ __forceinline__ void mma_tf32(float c[4], const uint32_t a[4],
                                         const uint32_t b[2]) {
    asm volatile(
        "mma.sync.aligned.m16n8k8.row.col.f32.tf32.tf32.f32 "
        "{%0,%1,%2,%3}, {%4,%5,%6,%7}, {%8,%9}, {%0,%1,%2,%3};"
        : "+f"(c[0]), "+f"(c[1]), "+f"(c[2]), "+f"(c[3])
        : "r"(a[0]), "r"(a[1]), "r"(a[2]), "r"(a[3]), "r"(b[0]), "r"(b[1]));
}

// ---------------------------------------------------------------------------
// Projection GEMM (3-pass compensated tf32): C = A[M,K] @ W[K,N].
// CTA tile 128 x CTA_N, BK=16, cp.async double buffer, 8 warps (2m x 4n).
// blockIdx.z selects (B0,C0) or (B1,C1) so K/V projections share one launch.
// ---------------------------------------------------------------------------
template <int CTA_N, int WNT>
__global__ __launch_bounds__(256) void proj_mma(
    const float* __restrict__ A,
    const float* __restrict__ B0, float* __restrict__ C0,
    const float* __restrict__ B1, float* __restrict__ C1,
    int N, int K)
{
    const float* Bg = blockIdx.z ? B1 : B0;
    float* C = blockIdx.z ? C1 : C0;

    __shared__ float As[2][128][20];
    __shared__ float Bs[2][16][CTA_N + 4];

    const int tid  = threadIdx.x;
    const int lane = tid & 31;
    const int wid  = tid >> 5;
    const int wm   = wid >> 2;
    const int wn   = wid & 3;
    const int tr   = lane >> 2;
    const int tc   = lane & 3;
    const int m0   = blockIdx.y * 128;
    const int n0   = blockIdx.x * CTA_N;

    float acc[4][WNT][4];
#pragma unroll
    for (int mt = 0; mt < 4; mt++)
#pragma unroll
        for (int nt = 0; nt < WNT; nt++)
#pragma unroll
            for (int q = 0; q < 4; q++) acc[mt][nt][q] = 0.0f;

    const int nch = K / 16;

    auto load_tile = [&](int c) {
        const int buf = c & 1;
        const int k0 = c * 16;
#pragma unroll
        for (int i = tid; i < 512; i += 256) {
            int r = i >> 2, q = i & 3;
            uint32_t s = (uint32_t)__cvta_generic_to_shared(&As[buf][r][q * 4]);
            CP_ASYNC16(s, A + (size_t)(m0 + r) * K + k0 + q * 4);
        }
#pragma unroll
        for (int i = tid; i < 16 * (CTA_N / 4); i += 256) {
            int r = i / (CTA_N / 4), q = i % (CTA_N / 4);
            uint32_t s = (uint32_t)__cvta_generic_to_shared(&Bs[buf][r][q * 4]);
            CP_ASYNC16(s, Bg + (size_t)(k0 + r) * N + n0 + q * 4);
        }
    };

    load_tile(0);
    CP_COMMIT();

    for (int c = 0; c < nch; c++) {
        if (c + 1 < nch) { load_tile(c + 1); CP_COMMIT(); CP_WAIT(1); }
        else             { CP_WAIT(0); }
        __syncthreads();

        const int buf = c & 1;
#pragma unroll
        for (int ks = 0; ks < 16; ks += 8) {
            uint32_t ah[4][4], al[4][4];
#pragma unroll
            for (int mt = 0; mt < 4; mt++) {
                int r = wm * 64 + mt * 16 + tr;
                split_tf32(As[buf][r][ks + tc],         ah[mt][0], al[mt][0]);
                split_tf32(As[buf][r + 8][ks + tc],     ah[mt][1], al[mt][1]);
                split_tf32(As[buf][r][ks + tc + 4],     ah[mt][2], al[mt][2]);
                split_tf32(As[buf][r + 8][ks + tc + 4], ah[mt][3], al[mt][3]);
            }
            uint32_t bh[WNT][2], bl[WNT][2];
#pragma unroll
            for (int nt = 0; nt < WNT; nt++) {
                int col = wn * (8 * WNT) + nt * 8 + tr;
                split_tf32(Bs[buf][ks + tc][col],     bh[nt][0], bl[nt][0]);
                split_tf32(Bs[buf][ks + tc + 4][col], bh[nt][1], bl[nt][1]);
            }
#pragma unroll
            for (int mt = 0; mt < 4; mt++)
#pragma unroll
                for (int nt = 0; nt < WNT; nt++) {
                    mma_tf32(acc[mt][nt], ah[mt], bh[nt]);
                    mma_tf32(acc[mt][nt], ah[mt], bl[nt]);
                    mma_tf32(acc[mt][nt], al[mt], bh[nt]);
                }
        }
        __syncthreads();
    }

#pragma unroll
    for (int mt = 0; mt < 4; mt++) {
        int r0 = m0 + wm * 64 + mt * 16 + tr;
#pragma unroll
        for (int nt = 0; nt < WNT; nt++) {
            int col = n0 + wn * (8 * WNT) + nt * 8 + 2 * tc;
            *(float2*)(C + (size_t)r0 * N + col) =
                make_float2(acc[mt][nt][0], acc[mt][nt][1]);
            *(float2*)(C + (size_t)(r0 + 8) * N + col) =
                make_float2(acc[mt][nt][2], acc[mt][nt][3]);
        }
    }
}

// ---------------------------------------------------------------------------
// Flash attention on mma.sync tf32. CTA: 128 queries x one head, 8 warps,
// each warp owns 16 query rows. Key tiles of 64. QK^T: 3-pass compensated
// tf32; PV: single-pass tf32 (P in [0,1]). P stays in registers and is
// moved from C-fragment to A-fragment layout with shuffles.
// smem floats: Qs[128][68] raw fp32 (pre-scaled), Ks[64][68] raw fp32,
// Vs[64][72] tf32-bit floats. Pads chosen conflict-free per access pattern.
// ---------------------------------------------------------------------------
#define QT 128
#define QS_OFF 0
#define KS_OFF (128 * 68)
#define VS_OFF (128 * 68 + 64 * 68)
#define FLASH_SMEM ((128 * 68 + 64 * 68 + 64 * 72) * 4)

extern __shared__ float fsm[];

__global__ __launch_bounds__(256) void flash_mqa(
    const float* __restrict__ Qg, const float* __restrict__ Kg,
    const float* __restrict__ Vg, float* __restrict__ out)
{
    float* Qs = fsm + QS_OFF;
    float* Ks = fsm + KS_OFF;
    float* Vs = fsm + VS_OFF;

    const int tid  = threadIdx.x;
    const int lane = tid & 31;
    const int w    = tid >> 5;
    const int tr   = lane >> 2;
    const int tc   = lane & 3;
    const int q0   = blockIdx.x * QT;
    const int h    = blockIdx.y;
    const int b    = blockIdx.z;
    const int qw0  = q0 + w * 16;

    // Q tile: pre-scale by 1/sqrt(64)=0.125 (exact), keep fp32 for hi/lo split
    for (int e = tid; e < 128 * 16; e += 256) {
        int r = e >> 4, dq = e & 15;
        float4 v = *(const float4*)(Qg + (size_t)(b * SEQ + q0 + r) * EMB + h * HDIM + dq * 4);
        v.x *= 0.125f; v.y *= 0.125f; v.z *= 0.125f; v.w *= 0.125f;
        *(float4*)(Qs + r * 68 + dq * 4) = v;
    }

    float m0 = -CUDART_INF_F, m1 = -CUDART_INF_F, l0 = 0.0f, l1 = 0.0f;
    float o[8][4];
    float s[8][4];
#pragma unroll
    for (int nt = 0; nt < 8; nt++)
#pragma unroll
        for (int j = 0; j < 4; j++) o[nt][j] = 0.0f;

    const int ktm = q0 / 64 + 1;
    for (int kt = 0; kt <= ktm; kt++) {
        const int k0 = kt * 64;
        __syncthreads();
        for (int e = tid; e < 64 * 16; e += 256) {
            int r = e >> 4, dq = e & 15;
            float4 kv = *(const float4*)(Kg + (size_t)(b * SEQ + k0 + r) * HDIM + dq * 4);
            *(float4*)(Ks + r * 68 + dq * 4) = kv;
            float4 vv = *(const float4*)(Vg + (size_t)(b * SEQ + k0 + r) * HDIM + dq * 4);
            vv.x = __uint_as_float(f2tf32(vv.x));
            vv.y = __uint_as_float(f2tf32(vv.y));
            vv.z = __uint_as_float(f2tf32(vv.z));
            vv.w = __uint_as_float(f2tf32(vv.w));
            *(float4*)(Vs + r * 72 + dq * 4) = vv;
        }
        __syncthreads();

        if (k0 > qw0 + 15) continue;   // warp-uniform; still hits top syncs

        // ---- S = Q K^T (3-pass tf32) ----
#pragma unroll
        for (int nt = 0; nt < 8; nt++)
#pragma unroll
            for (int j = 0; j < 4; j++) s[nt][j] = 0.0f;

#pragma unroll
        for (int kc = 0; kc < 8; kc++) {
            uint32_t ah[4], al[4];
            const float* qr0 = Qs + (w * 16 + tr) * 68 + kc * 8 + tc;
            const float* qr1 = qr0 + 8 * 68;
            split_tf32(qr0[0], ah[0], al[0]);
            split_tf32(qr1[0], ah[1], al[1]);
            split_tf32(qr0[4], ah[2], al[2]);
            split_tf32(qr1[4], ah[3], al[3]);
#pragma unroll
            for (int nt = 0; nt < 8; nt++) {
                const float* kr = Ks + (nt * 8 + tr) * 68 + kc * 8 + tc;
                uint32_t bh[2], bl[2];
                split_tf32(kr[0], bh[0], bl[0]);
                split_tf32(kr[4], bh[1], bl[1]);
                mma_tf32(s[nt], ah, bh);
                mma_tf32(s[nt], ah, bl);
                mma_tf32(s[nt], al, bh);
            }
        }

        // ---- causal mask (only the diagonal-crossing tile) ----
        if (k0 + 63 > qw0) {
#pragma unroll
            for (int nt = 0; nt < 8; nt++) {
                int key0 = k0 + nt * 8 + 2 * tc;
                int r0 = qw0 + tr, r1 = r0 + 8;
                if (key0 > r0)     s[nt][0] = -CUDART_INF_F;
                if (key0 + 1 > r0) s[nt][1] = -CUDART_INF_F;
                if (key0 > r1)     s[nt][2] = -CUDART_INF_F;
                if (key0 + 1 > r1) s[nt][3] = -CUDART_INF_F;
            }
        }

        // ---- online softmax ----
        float mx0 = -CUDART_INF_F, mx1 = -CUDART_INF_F;
#pragma unroll
        for (int nt = 0; nt < 8; nt++) {
            mx0 = fmaxf(mx0, fmaxf(s[nt][0], s[nt][1]));
            mx1 = fmaxf(mx1, fmaxf(s[nt][2], s[nt][3]));
        }
        mx0 = fmaxf(mx0, __shfl_xor_sync(0xffffffffu, mx0, 1));
        mx0 = fmaxf(mx0, __shfl_xor_sync(0xffffffffu, mx0, 2));
        mx1 = fmaxf(mx1, __shfl_xor_sync(0xffffffffu, mx1, 1));
        mx1 = fmaxf(mx1, __shfl_xor_sync(0xffffffffu, mx1, 2));

        float mn0 = fmaxf(m0, mx0), mn1 = fmaxf(m1, mx1);
        float c0 = __expf(m0 - mn0), c1 = __expf(m1 - mn1);
        m0 = mn0; m1 = mn1;

        float ls0 = 0.0f, ls1 = 0.0f;
#pragma unroll
        for (int nt = 0; nt < 8; nt++) {
            float p0 = __expf(s[nt][0] - mn0);
            float p1 = __expf(s[nt][1] - mn0);
            float p2 = __expf(s[nt][2] - mn1);
            float p3 = __expf(s[nt][3] - mn1);
            ls0 += p0 + p1;
            ls1 += p2 + p3;
            s[nt][0] = __uint_as_float(f2tf32(p0));
            s[nt][1] = __uint_as_float(f2tf32(p1));
            s[nt][2] = __uint_as_float(f2tf32(p2));
            s[nt][3] = __uint_as_float(f2tf32(p3));
        }
        ls0 += __shfl_xor_sync(0xffffffffu, ls0, 1);
        ls0 += __shfl_xor_sync(0xffffffffu, ls0, 2);
        ls1 += __shfl_xor_sync(0xffffffffu, ls1, 1);
        ls1 += __shfl_xor_sync(0xffffffffu, ls1, 2);
        l0 = l0 * c0 + ls0;
        l1 = l1 * c1 + ls1;

#pragma unroll
        for (int nt = 0; nt < 8; nt++) {
            o[nt][0] *= c0; o[nt][1] *= c0;
            o[nt][2] *= c1; o[nt][3] *= c1;
        }

        // ---- O += P V (single-pass tf32); P C-frag -> A-frag via shuffles ----
        const int src  = 4 * tr + (tc >> 1);
        const int src2 = src + 2;
        const bool odd = tc & 1;
#pragma unroll
        for (int kc = 0; kc < 8; kc++) {
            float u0 = __shfl_sync(0xffffffffu, s[kc][0], src);
            float u1 = __shfl_sync(0xffffffffu, s[kc][1], src);
            float v0 = __shfl_sync(0xffffffffu, s[kc][0], src2);
            float v1 = __shfl_sync(0xffffffffu, s[kc][1], src2);
            float w0 = __shfl_sync(0xffffffffu, s[kc][2], src);
            float w1 = __shfl_sync(0xffffffffu, s[kc][3], src);
            float x0 = __shfl_sync(0xffffffffu, s[kc][2], src2);
            float x1 = __shfl_sync(0xffffffffu, s[kc][3], src2);
            uint32_t a[4];
            a[0] = __float_as_uint(odd ? u1 : u0);
            a[1] = __float_as_uint(odd ? w1 : w0);
            a[2] = __float_as_uint(odd ? v1 : v0);
            a[3] = __float_as_uint(odd ? x1 : x0);
#pragma unroll
            for (int nt = 0; nt < 8; nt++) {
                uint32_t bv[2];
                bv[0] = __float_as_uint(Vs[(kc * 8 + tc) * 72 + nt * 8 + tr]);
                bv[1] = __float_as_uint(Vs[(kc * 8 + tc + 4) * 72 + nt * 8 + tr]);
                mma_tf32(o[nt], a, bv);
            }
        }
    }

    // ---- epilogue ----
    const float inv0 = 1.0f / l0, inv1 = 1.0f / l1;
    const size_t gr0 = (size_t)(b * SEQ + qw0 + tr) * EMB + h * HDIM;
    const size_t gr1 = gr0 + 8 * EMB;
#pragma unroll
    for (int nt = 0; nt < 8; nt++) {
        int col = nt * 8 + 2 * tc;
        *(float2*)(out + gr0 + col) = make_float2(o[nt][0] * inv0, o[nt][1] * inv0);
        *(float2*)(out + gr1 + col) = make_float2(o[nt][2] * inv1, o[nt][3] * inv1);
    }
}

// ---------------------------------------------------------------------------
// Launch
// ---------------------------------------------------------------------------
extern "C" void kernel_launch(void* const* d_in, const int* in_sizes, int n_in,
                              void* d_out, int out_size)
{
    const float* X  = (const float*)d_in[0];
    const float* Wq = (const float*)d_in[1];
    const float* Wk = (const float*)d_in[2];
    const float* Wv = (const float*)d_in[3];
    float* out = (float*)d_out;

    float *Qbuf, *Kbuf, *Vbuf;
    cudaGetSymbolAddress((void**)&Qbuf, g_Q);
    cudaGetSymbolAddress((void**)&Kbuf, g_K);
    cudaGetSymbolAddress((void**)&Vbuf, g_V);

    {
        dim3 blk(256);
        dim3 gq(EMB / 128, ROWS / 128, 1);   // (8, 32, 1)
        proj_mma<128, 4><<<gq, blk>>>(X, Wq, Qbuf, Wq, Qbuf, EMB, EMB);
        dim3 gkv(1, ROWS / 128, 2);          // K and V in one launch
        proj_mma<64, 2><<<gkv, blk>>>(X, Wk, Kbuf, Wv, Vbuf, HDIM, EMB);
    }

    {
        cudaFuncSetAttribute(flash_mqa, cudaFuncAttributeMaxDynamicSharedMemorySize, FLASH_SMEM);
        dim3 blk(256);
        dim3 grid(SEQ / QT, HEADS, BATCH);   // (16, 16, 2)
        flash_mqa<<<grid, blk, FLASH_SMEM>>>(Qbuf, Kbuf, Vbuf, out);
    }
}

// round 7
// speedup vs baseline: 2.7302x; 1.2169x over previous
#include <cuda_runtime.h>
#include <cuda_bf16.h>
#include <math_constants.h>
#include <cstdint>

#define BATCH 2
#define SEQ   2048
#define EMB   1024
#define HEADS 16
#define HDIM  64
#define ROWS  (BATCH * SEQ)   // 4096

__device__ float g_Q[ROWS * EMB];
__device__ float g_K[ROWS * HDIM];
__device__ float g_V[ROWS * HDIM];

// ---------------------------------------------------------------------------
// Helpers
// ---------------------------------------------------------------------------
__device__ __forceinline__ uint32_t f2tf32(float x) {
    uint32_t u;
    asm("cvt.rna.tf32.f32 %0, %1;" : "=r"(u) : "f"(x));
    return u;
}

// Compensated split: x ~= hi + lo, both tf32-representable.
__device__ __forceinline__ void split_tf32(float x, uint32_t& h, uint32_t& l) {
    h = f2tf32(x);
    float r = x - __uint_as_float(h);
    l = f2tf32(r);
}

// Fast 2^x for x <= 0 on the FMA pipe (no MUFU). |rel err| <= ~2e-5.
__device__ __forceinline__ float ex2_fast(float x) {
    x = fmaxf(x, -100.0f);
    float fl = floorf(x);
    float f = x - fl;                  // [0,1)
    float p = 0.000154035304f;         // Taylor ln2^k/k!, k=6..0
    p = fmaf(p, f, 0.00133335581f);
    p = fmaf(p, f, 0.00961812911f);
    p = fmaf(p, f, 0.0555041087f);
    p = fmaf(p, f, 0.240226507f);
    p = fmaf(p, f, 0.693147182f);
    p = fmaf(p, f, 1.0f);              // p in [1,2)
    int e = (int)fl;                   // exact integer, >= -100
    return __int_as_float(__float_as_int(p) + (e << 23));
}

#define CP_ASYNC16(saddr, gptr) \
    asm volatile("cp.async.cg.shared.global [%0], [%1], 16;" \
                 :: "r"(saddr), "l"(gptr))
#define CP_COMMIT() asm volatile("cp.async.commit_group;" ::: "memory")
#define CP_WAIT(n)  asm volatile("cp.async.wait_group %0;" :: "n"(n) : "memory")

__device__ __forceinline__ void mma_tf32(float c[4], const uint32_t a[4],
                                         const uint32_t b[2]) {
    asm volatile(
        "mma.sync.aligned.m16n8k8.row.col.f32.tf32.tf32.f32 "
        "{%0,%1,%2,%3}, {%4,%5,%6,%7}, {%8,%9}, {%0,%1,%2,%3};"
        : "+f"(c[0]), "+f"(c[1]), "+f"(c[2]), "+f"(c[3])
        : "r"(a[0]), "r"(a[1]), "r"(a[2]), "r"(a[3]), "r"(b[0]), "r"(b[1]));
}

// ---------------------------------------------------------------------------
// Projection GEMM (3-pass compensated tf32): C = A[M,K] @ W[K,N].
// CTA tile 128 x CTA_N, BK=16, cp.async double buffer, 8 warps (2m x 4n).
// blockIdx.z selects (B0,C0) or (B1,C1) so K/V projections share one launch.
// ---------------------------------------------------------------------------
template <int CTA_N, int WNT>
__global__ __launch_bounds__(256) void proj_mma(
    const float* __restrict__ A,
    const float* __restrict__ B0, float* __restrict__ C0,
    const float* __restrict__ B1, float* __restrict__ C1,
    int N, int K)
{
    const float* Bg = blockIdx.z ? B1 : B0;
    float* C = blockIdx.z ? C1 : C0;

    __shared__ float As[2][128][20];
    __shared__ float Bs[2][16][CTA_N + 4];

    const int tid  = threadIdx.x;
    const int lane = tid & 31;
    const int wid  = tid >> 5;
    const int wm   = wid >> 2;
    const int wn   = wid & 3;
    const int tr   = lane >> 2;
    const int tc   = lane & 3;
    const int m0   = blockIdx.y * 128;
    const int n0   = blockIdx.x * CTA_N;

    float acc[4][WNT][4];
#pragma unroll
    for (int mt = 0; mt < 4; mt++)
#pragma unroll
        for (int nt = 0; nt < WNT; nt++)
#pragma unroll
            for (int q = 0; q < 4; q++) acc[mt][nt][q] = 0.0f;

    const int nch = K / 16;

    auto load_tile = [&](int c) {
        const int buf = c & 1;
        const int k0 = c * 16;
#pragma unroll
        for (int i = tid; i < 512; i += 256) {
            int r = i >> 2, q = i & 3;
            uint32_t s = (uint32_t)__cvta_generic_to_shared(&As[buf][r][q * 4]);
            CP_ASYNC16(s, A + (size_t)(m0 + r) * K + k0 + q * 4);
        }
#pragma unroll
        for (int i = tid; i < 16 * (CTA_N / 4); i += 256) {
            int r = i / (CTA_N / 4), q = i % (CTA_N / 4);
            uint32_t s = (uint32_t)__cvta_generic_to_shared(&Bs[buf][r][q * 4]);
            CP_ASYNC16(s, Bg + (size_t)(k0 + r) * N + n0 + q * 4);
        }
    };

    load_tile(0);
    CP_COMMIT();

    for (int c = 0; c < nch; c++) {
        if (c + 1 < nch) { load_tile(c + 1); CP_COMMIT(); CP_WAIT(1); }
        else             { CP_WAIT(0); }
        __syncthreads();

        const int buf = c & 1;
#pragma unroll
        for (int ks = 0; ks < 16; ks += 8) {
            uint32_t ah[4][4], al[4][4];
#pragma unroll
            for (int mt = 0; mt < 4; mt++) {
                int r = wm * 64 + mt * 16 + tr;
                split_tf32(As[buf][r][ks + tc],         ah[mt][0], al[mt][0]);
                split_tf32(As[buf][r + 8][ks + tc],     ah[mt][1], al[mt][1]);
                split_tf32(As[buf][r][ks + tc + 4],     ah[mt][2], al[mt][2]);
                split_tf32(As[buf][r + 8][ks + tc + 4], ah[mt][3], al[mt][3]);
            }
            uint32_t bh[WNT][2], bl[WNT][2];
#pragma unroll
            for (int nt = 0; nt < WNT; nt++) {
                int col = wn * (8 * WNT) + nt * 8 + tr;
                split_tf32(Bs[buf][ks + tc][col],     bh[nt][0], bl[nt][0]);
                split_tf32(Bs[buf][ks + tc + 4][col], bh[nt][1], bl[nt][1]);
            }
#pragma unroll
            for (int mt = 0; mt < 4; mt++)
#pragma unroll
                for (int nt = 0; nt < WNT; nt++) {
                    mma_tf32(acc[mt][nt], ah[mt], bh[nt]);
                    mma_tf32(acc[mt][nt], ah[mt], bl[nt]);
                    mma_tf32(acc[mt][nt], al[mt], bh[nt]);
                }
        }
        __syncthreads();
    }

#pragma unroll
    for (int mt = 0; mt < 4; mt++) {
        int r0 = m0 + wm * 64 + mt * 16 + tr;
#pragma unroll
        for (int nt = 0; nt < WNT; nt++) {
            int col = n0 + wn * (8 * WNT) + nt * 8 + 2 * tc;
            *(float2*)(C + (size_t)r0 * N + col) =
                make_float2(acc[mt][nt][0], acc[mt][nt][1]);
            *(float2*)(C + (size_t)(r0 + 8) * N + col) =
                make_float2(acc[mt][nt][2], acc[mt][nt][3]);
        }
    }
}

// ---------------------------------------------------------------------------
// Flash attention on mma.sync tf32, log2-domain softmax.
// CTA: 128 queries x one head, 8 warps x 16 query rows. Key tiles of 64.
// QK^T: single-pass tf32 (Q pre-scaled by 0.125*log2e); softmax uses the
// FMA-pipe ex2_fast (no MUFU). PV: single-pass tf32, P kept in registers and
// moved C-frag -> A-frag with shuffles.
// smem: Qs[128][68], Ks[64][68], Vs[64][72] -- all tf32-bit floats,
// pads conflict-free per access pattern.
// ---------------------------------------------------------------------------
#define QT 128
#define QS_OFF 0
#define KS_OFF (128 * 68)
#define VS_OFF (128 * 68 + 64 * 68)
#define FLASH_SMEM ((128 * 68 + 64 * 68 + 64 * 72) * 4)
#define QSCALE 0.180336880111120f   // 0.125 * log2(e)

extern __shared__ float fsm[];

__global__ __launch_bounds__(256) void flash_mqa(
    const float* __restrict__ Qg, const float* __restrict__ Kg,
    const float* __restrict__ Vg, float* __restrict__ out)
{
    float* Qs = fsm + QS_OFF;
    float* Ks = fsm + KS_OFF;
    float* Vs = fsm + VS_OFF;

    const int tid  = threadIdx.x;
    const int lane = tid & 31;
    const int w    = tid >> 5;
    const int tr   = lane >> 2;
    const int tc   = lane & 3;
    const int q0   = blockIdx.x * QT;
    const int h    = blockIdx.y;
    const int b    = blockIdx.z;
    const int qw0  = q0 + w * 16;

    // Q tile: fold softmax scale + log2e, convert to tf32 bits at load.
    for (int e = tid; e < 128 * 16; e += 256) {
        int r = e >> 4, dq = e & 15;
        float4 v = *(const float4*)(Qg + (size_t)(b * SEQ + q0 + r) * EMB + h * HDIM + dq * 4);
        v.x = __uint_as_float(f2tf32(v.x * QSCALE));
        v.y = __uint_as_float(f2tf32(v.y * QSCALE));
        v.z = __uint_as_float(f2tf32(v.z * QSCALE));
        v.w = __uint_as_float(f2tf32(v.w * QSCALE));
        *(float4*)(Qs + r * 68 + dq * 4) = v;
    }

    float m0 = -CUDART_INF_F, m1 = -CUDART_INF_F, l0 = 0.0f, l1 = 0.0f;
    float o[8][4];
    float s[8][4];
#pragma unroll
    for (int nt = 0; nt < 8; nt++)
#pragma unroll
        for (int j = 0; j < 4; j++) o[nt][j] = 0.0f;

    const int ktm = q0 / 64 + 1;
    for (int kt = 0; kt <= ktm; kt++) {
        const int k0 = kt * 64;
        __syncthreads();
        for (int e = tid; e < 64 * 16; e += 256) {
            int r = e >> 4, dq = e & 15;
            float4 kv = *(const float4*)(Kg + (size_t)(b * SEQ + k0 + r) * HDIM + dq * 4);
            kv.x = __uint_as_float(f2tf32(kv.x));
            kv.y = __uint_as_float(f2tf32(kv.y));
            kv.z = __uint_as_float(f2tf32(kv.z));
            kv.w = __uint_as_float(f2tf32(kv.w));
            *(float4*)(Ks + r * 68 + dq * 4) = kv;
            float4 vv = *(const float4*)(Vg + (size_t)(b * SEQ + k0 + r) * HDIM + dq * 4);
            vv.x = __uint_as_float(f2tf32(vv.x));
            vv.y = __uint_as_float(f2tf32(vv.y));
            vv.z = __uint_as_float(f2tf32(vv.z));
            vv.w = __uint_as_float(f2tf32(vv.w));
            *(float4*)(Vs + r * 72 + dq * 4) = vv;
        }
        __syncthreads();

        if (k0 > qw0 + 15) continue;   // warp-uniform; still hits top syncs

        // ---- S = Q K^T (single-pass tf32, log2 domain) ----
#pragma unroll
        for (int nt = 0; nt < 8; nt++)
#pragma unroll
            for (int j = 0; j < 4; j++) s[nt][j] = 0.0f;

#pragma unroll
        for (int kc = 0; kc < 8; kc++) {
            uint32_t a[4];
            const float* qr0 = Qs + (w * 16 + tr) * 68 + kc * 8 + tc;
            const float* qr1 = qr0 + 8 * 68;
            a[0] = __float_as_uint(qr0[0]);
            a[1] = __float_as_uint(qr1[0]);
            a[2] = __float_as_uint(qr0[4]);
            a[3] = __float_as_uint(qr1[4]);
#pragma unroll
            for (int nt = 0; nt < 8; nt++) {
                const float* kr = Ks + (nt * 8 + tr) * 68 + kc * 8 + tc;
                uint32_t bk[2];
                bk[0] = __float_as_uint(kr[0]);
                bk[1] = __float_as_uint(kr[4]);
                mma_tf32(s[nt], a, bk);
            }
        }

        // ---- causal mask (only the diagonal-crossing tile) ----
        if (k0 + 63 > qw0) {
#pragma unroll
            for (int nt = 0; nt < 8; nt++) {
                int key0 = k0 + nt * 8 + 2 * tc;
                int r0 = qw0 + tr, r1 = r0 + 8;
                if (key0 > r0)     s[nt][0] = -CUDART_INF_F;
                if (key0 + 1 > r0) s[nt][1] = -CUDART_INF_F;
                if (key0 > r1)     s[nt][2] = -CUDART_INF_F;
                if (key0 + 1 > r1) s[nt][3] = -CUDART_INF_F;
            }
        }

        // ---- online softmax (log2 domain, FMA-pipe ex2) ----
        float mx0 = -CUDART_INF_F, mx1 = -CUDART_INF_F;
#pragma unroll
        for (int nt = 0; nt < 8; nt++) {
            mx0 = fmaxf(mx0, fmaxf(s[nt][0], s[nt][1]));
            mx1 = fmaxf(mx1, fmaxf(s[nt][2], s[nt][3]));
        }
        mx0 = fmaxf(mx0, __shfl_xor_sync(0xffffffffu, mx0, 1));
        mx0 = fmaxf(mx0, __shfl_xor_sync(0xffffffffu, mx0, 2));
        mx1 = fmaxf(mx1, __shfl_xor_sync(0xffffffffu, mx1, 1));
        mx1 = fmaxf(mx1, __shfl_xor_sync(0xffffffffu, mx1, 2));

        float mn0 = fmaxf(m0, mx0), mn1 = fmaxf(m1, mx1);
        float c0 = ex2_fast(m0 - mn0), c1 = ex2_fast(m1 - mn1);
        m0 = mn0; m1 = mn1;

        float ls0 = 0.0f, ls1 = 0.0f;
#pragma unroll
        for (int nt = 0; nt < 8; nt++) {
            float p0 = ex2_fast(s[nt][0] - mn0);
            float p1 = ex2_fast(s[nt][1] - mn0);
            float p2 = ex2_fast(s[nt][2] - mn1);
            float p3 = ex2_fast(s[nt][3] - mn1);
            ls0 += p0 + p1;
            ls1 += p2 + p3;
            s[nt][0] = __uint_as_float(f2tf32(p0));
            s[nt][1] = __uint_as_float(f2tf32(p1));
            s[nt][2] = __uint_as_float(f2tf32(p2));
            s[nt][3] = __uint_as_float(f2tf32(p3));
        }
        ls0 += __shfl_xor_sync(0xffffffffu, ls0, 1);
        ls0 += __shfl_xor_sync(0xffffffffu, ls0, 2);
        ls1 += __shfl_xor_sync(0xffffffffu, ls1, 1);
        ls1 += __shfl_xor_sync(0xffffffffu, ls1, 2);
        l0 = l0 * c0 + ls0;
        l1 = l1 * c1 + ls1;

#pragma unroll
        for (int nt = 0; nt < 8; nt++) {
            o[nt][0] *= c0; o[nt][1] *= c0;
            o[nt][2] *= c1; o[nt][3] *= c1;
        }

        // ---- O += P V (single-pass tf32); P C-frag -> A-frag via shuffles ----
        const int src  = 4 * tr + (tc >> 1);
        const int src2 = src + 2;
        const bool odd = tc & 1;
#pragma unroll
        for (int kc = 0; kc < 8; kc++) {
            float u0 = __shfl_sync(0xffffffffu, s[kc][0], src);
            float u1 = __shfl_sync(0xffffffffu, s[kc][1], src);
            float v0 = __shfl_sync(0xffffffffu, s[kc][0], src2);
            float v1 = __shfl_sync(0xffffffffu, s[kc][1], src2);
            float w0 = __shfl_sync(0xffffffffu, s[kc][2], src);
            float w1 = __shfl_sync(0xffffffffu, s[kc][3], src);
            float x0 = __shfl_sync(0xffffffffu, s[kc][2], src2);
            float x1 = __shfl_sync(0xffffffffu, s[kc][3], src2);
            uint32_t a[4];
            a[0] = __float_as_uint(odd ? u1 : u0);
            a[1] = __float_as_uint(odd ? w1 : w0);
            a[2] = __float_as_uint(odd ? v1 : v0);
            a[3] = __float_as_uint(odd ? x1 : x0);
#pragma unroll
            for (int nt = 0; nt < 8; nt++) {
                uint32_t bv[2];
                bv[0] = __float_as_uint(Vs[(kc * 8 + tc) * 72 + nt * 8 + tr]);
                bv[1] = __float_as_uint(Vs[(kc * 8 + tc + 4) * 72 + nt * 8 + tr]);
                mma_tf32(o[nt], a, bv);
            }
        }
    }

    // ---- epilogue ----
    const float inv0 = 1.0f / l0, inv1 = 1.0f / l1;
    const size_t gr0 = (size_t)(b * SEQ + qw0 + tr) * EMB + h * HDIM;
    const size_t gr1 = gr0 + 8 * EMB;
#pragma unroll
    for (int nt = 0; nt < 8; nt++) {
        int col = nt * 8 + 2 * tc;
        *(float2*)(out + gr0 + col) = make_float2(o[nt][0] * inv0, o[nt][1] * inv0);
        *(float2*)(out + gr1 + col) = make_float2(o[nt][2] * inv1, o[nt][3] * inv1);
    }
}

// ---------------------------------------------------------------------------
// Launch
// ---------------------------------------------------------------------------
extern "C" void kernel_launch(void* const* d_in, const int* in_sizes, int n_in,
                              void* d_out, int out_size)
{
    const float* X  = (const float*)d_in[0];
    const float* Wq = (const float*)d_in[1];
    const float* Wk = (const float*)d_in[2];
    const float* Wv = (const float*)d_in[3];
    float* out = (float*)d_out;

    float *Qbuf, *Kbuf, *Vbuf;
    cudaGetSymbolAddress((void**)&Qbuf, g_Q);
    cudaGetSymbolAddress((void**)&Kbuf, g_K);
    cudaGetSymbolAddress((void**)&Vbuf, g_V);

    {
        dim3 blk(256);
        dim3 gq(EMB / 128, ROWS / 128, 1);   // (8, 32, 1)
        proj_mma<128, 4><<<gq, blk>>>(X, Wq, Qbuf, Wq, Qbuf, EMB, EMB);
        dim3 gkv(1, ROWS / 128, 2);          // K and V in one launch
        proj_mma<64, 2><<<gkv, blk>>>(X, Wk, Kbuf, Wv, Vbuf, HDIM, EMB);
    }

    {
        cudaFuncSetAttribute(flash_mqa, cudaFuncAttributeMaxDynamicSharedMemorySize, FLASH_SMEM);
        dim3 blk(256);
        dim3 grid(SEQ / QT, HEADS, BATCH);   // (16, 16, 2)
        flash_mqa<<<grid, blk, FLASH_SMEM>>>(Qbuf, Kbuf, Vbuf, out);
    }
}

// round 10
// speedup vs baseline: 3.6955x; 1.3535x over previous
#include <cuda_runtime.h>
#include <cuda_bf16.h>
#include <math_constants.h>
#include <cstdint>

#define BATCH 2
#define SEQ   2048
#define EMB   1024
#define HEADS 16
#define HDIM  64
#define ROWS  (BATCH * SEQ)   // 4096

__device__ float g_Q[ROWS * EMB];
__device__ float g_K[ROWS * HDIM];
__device__ float g_V[ROWS * HDIM];

// ---------------------------------------------------------------------------
// Helpers
// ---------------------------------------------------------------------------
__device__ __forceinline__ uint32_t f2tf32(float x) {
    uint32_t u;
    asm("cvt.rna.tf32.f32 %0, %1;" : "=r"(u) : "f"(x));
    return u;
}

// bf16 split of a float pair: hi = packed bf16x2 of (x0,x1),
// lo = packed bf16x2 of the residuals. (x0 -> low half, x1 -> high half)
__device__ __forceinline__ void split2_bf16(float x0, float x1,
                                            uint32_t& hi, uint32_t& lo) {
    asm("cvt.rn.bf16x2.f32 %0, %1, %2;" : "=r"(hi) : "f"(x1), "f"(x0));
    float h0 = __uint_as_float(hi << 16);
    float h1 = __uint_as_float(hi & 0xFFFF0000u);
    float r0 = x0 - h0;
    float r1 = x1 - h1;
    asm("cvt.rn.bf16x2.f32 %0, %1, %2;" : "=r"(lo) : "f"(r1), "f"(r0));
}

// Fast 2^x for x <= 0 on the FMA pipe (no MUFU). |rel err| <= ~2e-5.
__device__ __forceinline__ float ex2_fast(float x) {
    x = fmaxf(x, -100.0f);
    float fl = floorf(x);
    float f = x - fl;                  // [0,1)
    float p = 0.000154035304f;         // Taylor ln2^k/k!, k=6..0
    p = fmaf(p, f, 0.00133335581f);
    p = fmaf(p, f, 0.00961812911f);
    p = fmaf(p, f, 0.0555041087f);
    p = fmaf(p, f, 0.240226507f);
    p = fmaf(p, f, 0.693147182f);
    p = fmaf(p, f, 1.0f);              // p in [1,2)
    int e = (int)fl;
    return __int_as_float(__float_as_int(p) + (e << 23));
}

#define CP_ASYNC16(saddr, gptr) \
    asm volatile("cp.async.cg.shared.global [%0], [%1], 16;" \
                 :: "r"(saddr), "l"(gptr))
#define CP_COMMIT() asm volatile("cp.async.commit_group;" ::: "memory")
#define CP_WAIT(n)  asm volatile("cp.async.wait_group %0;" :: "n"(n) : "memory")

__device__ __forceinline__ void mma_tf32(float c[4], const uint32_t a[4],
                                         const uint32_t b[2]) {
    asm volatile(
        "mma.sync.aligned.m16n8k8.row.col.f32.tf32.tf32.f32 "
        "{%0,%1,%2,%3}, {%4,%5,%6,%7}, {%8,%9}, {%0,%1,%2,%3};"
        : "+f"(c[0]), "+f"(c[1]), "+f"(c[2]), "+f"(c[3])
        : "r"(a[0]), "r"(a[1]), "r"(a[2]), "r"(a[3]), "r"(b[0]), "r"(b[1]));
}

__device__ __forceinline__ void mma_bf16(float c[4], const uint32_t a[4],
                                         const uint32_t b[2]) {
    asm volatile(
        "mma.sync.aligned.m16n8k16.row.col.f32.bf16.bf16.f32 "
        "{%0,%1,%2,%3}, {%4,%5,%6,%7}, {%8,%9}, {%0,%1,%2,%3};"
        : "+f"(c[0]), "+f"(c[1]), "+f"(c[2]), "+f"(c[3])
        : "r"(a[0]), "r"(a[1]), "r"(a[2]), "r"(a[3]), "r"(b[0]), "r"(b[1]));
}

// ---------------------------------------------------------------------------
// Projection GEMM (bf16x3 compensated): C = A[M,K] @ W[K,N].
// hi/lo bf16 split; D = Ah*Bh + Ah*Bl + Al*Bh (lo*lo dropped, ~2^-18).
// CTA tile 128 x CTA_N, BK=16 (one m16n8k16 step), cp.async double buffer,
// 8 warps (2m x 4n). blockIdx.z selects (B0,C0)/(B1,C1).
// ---------------------------------------------------------------------------
template <int CTA_N, int WNT>
__global__ __launch_bounds__(256) void proj_mma(
    const float* __restrict__ A,
    const float* __restrict__ B0, float* __restrict__ C0,
    const float* __restrict__ B1, float* __restrict__ C1,
    int N, int K)
{
    const float* Bg = blockIdx.z ? B1 : B0;
    float* C = blockIdx.z ? C1 : C0;

    __shared__ float As[2][128][24];          // pad 24: float2 reads conflict-free
    __shared__ float Bs[2][16][CTA_N + 4];

    const int tid  = threadIdx.x;
    const int lane = tid & 31;
    const int wid  = tid >> 5;
    const int wm   = wid >> 2;
    const int wn   = wid & 3;
    const int tr   = lane >> 2;
    const int tc   = lane & 3;
    const int m0   = blockIdx.y * 128;
    const int n0   = blockIdx.x * CTA_N;

    float acc[4][WNT][4];
#pragma unroll
    for (int mt = 0; mt < 4; mt++)
#pragma unroll
        for (int nt = 0; nt < WNT; nt++)
#pragma unroll
            for (int q = 0; q < 4; q++) acc[mt][nt][q] = 0.0f;

    const int nch = K / 16;

    auto load_tile = [&](int c) {
        const int buf = c & 1;
        const int k0 = c * 16;
#pragma unroll
        for (int i = tid; i < 512; i += 256) {
            int r = i >> 2, q = i & 3;
            uint32_t s = (uint32_t)__cvta_generic_to_shared(&As[buf][r][q * 4]);
            CP_ASYNC16(s, A + (size_t)(m0 + r) * K + k0 + q * 4);
        }
#pragma unroll
        for (int i = tid; i < 16 * (CTA_N / 4); i += 256) {
            int r = i / (CTA_N / 4), q = i % (CTA_N / 4);
            uint32_t s = (uint32_t)__cvta_generic_to_shared(&Bs[buf][r][q * 4]);
            CP_ASYNC16(s, Bg + (size_t)(k0 + r) * N + n0 + q * 4);
        }
    };

    load_tile(0);
    CP_COMMIT();

    for (int c = 0; c < nch; c++) {
        if (c + 1 < nch) { load_tile(c + 1); CP_COMMIT(); CP_WAIT(1); }
        else             { CP_WAIT(0); }
        __syncthreads();

        const int buf = c & 1;

        uint32_t ah[4][4], al[4][4];
#pragma unroll
        for (int mt = 0; mt < 4; mt++) {
            int r = wm * 64 + mt * 16 + tr;
            float2 a00 = *(const float2*)&As[buf][r][2 * tc];
            float2 a01 = *(const float2*)&As[buf][r + 8][2 * tc];
            float2 a10 = *(const float2*)&As[buf][r][2 * tc + 8];
            float2 a11 = *(const float2*)&As[buf][r + 8][2 * tc + 8];
            split2_bf16(a00.x, a00.y, ah[mt][0], al[mt][0]);
            split2_bf16(a01.x, a01.y, ah[mt][1], al[mt][1]);
            split2_bf16(a10.x, a10.y, ah[mt][2], al[mt][2]);
            split2_bf16(a11.x, a11.y, ah[mt][3], al[mt][3]);
        }
        uint32_t bh[WNT][2], bl[WNT][2];
#pragma unroll
        for (int nt = 0; nt < WNT; nt++) {
            int col = wn * (8 * WNT) + nt * 8 + tr;
            split2_bf16(Bs[buf][2 * tc][col],     Bs[buf][2 * tc + 1][col],
                        bh[nt][0], bl[nt][0]);
            split2_bf16(Bs[buf][2 * tc + 8][col], Bs[buf][2 * tc + 9][col],
                        bh[nt][1], bl[nt][1]);
        }
#pragma unroll
        for (int mt = 0; mt < 4; mt++)
#pragma unroll
            for (int nt = 0; nt < WNT; nt++) {
                mma_bf16(acc[mt][nt], ah[mt], bh[nt]);
                mma_bf16(acc[mt][nt], ah[mt], bl[nt]);
                mma_bf16(acc[mt][nt], al[mt], bh[nt]);
            }
        __syncthreads();
    }

#pragma unroll
    for (int mt = 0; mt < 4; mt++) {
        int r0 = m0 + wm * 64 + mt * 16 + tr;
#pragma unroll
        for (int nt = 0; nt < WNT; nt++) {
            int col = n0 + wn * (8 * WNT) + nt * 8 + 2 * tc;
            *(float2*)(C + (size_t)r0 * N + col) =
                make_float2(acc[mt][nt][0], acc[mt][nt][1]);
            *(float2*)(C + (size_t)(r0 + 8) * N + col) =
                make_float2(acc[mt][nt][2], acc[mt][nt][3]);
        }
    }
}

// ---------------------------------------------------------------------------
// Flash attention on mma.sync tf32, log2-domain softmax, FMA-pipe exp.
// CTA: 128 queries x one head, 8 warps x 16 query rows; key tiles of 64.
// Work order reversed (heavy causal blocks first) for wave balance.
// Q fragments hoisted out of the key loop (loop-invariant).
// ---------------------------------------------------------------------------
#define QT 128
#define QS_OFF 0
#define KS_OFF (128 * 68)
#define VS_OFF (128 * 68 + 64 * 68)
#define FLASH_SMEM ((128 * 68 + 64 * 68 + 64 * 72) * 4)
#define QSCALE 0.180336880111120f   // 0.125 * log2(e)

extern __shared__ float fsm[];

__global__ __launch_bounds__(256) void flash_mqa(
    const float* __restrict__ Qg, const float* __restrict__ Kg,
    const float* __restrict__ Vg, float* __restrict__ out)
{
    float* Qs = fsm + QS_OFF;
    float* Ks = fsm + KS_OFF;
    float* Vs = fsm + VS_OFF;

    const int tid  = threadIdx.x;
    const int lane = tid & 31;
    const int w    = tid >> 5;
    const int tr   = lane >> 2;
    const int tc   = lane & 3;
    const int q0   = (gridDim.x - 1 - blockIdx.x) * QT;   // heavy blocks first
    const int h    = blockIdx.y;
    const int b    = blockIdx.z;
    const int qw0  = q0 + w * 16;

    // Q tile: fold softmax scale + log2e, convert to tf32 bits at load.
    for (int e = tid; e < 128 * 16; e += 256) {
        int r = e >> 4, dq = e & 15;
        float4 v = *(const float4*)(Qg + (size_t)(b * SEQ + q0 + r) * EMB + h * HDIM + dq * 4);
        v.x = __uint_as_float(f2tf32(v.x * QSCALE));
        v.y = __uint_as_float(f2tf32(v.y * QSCALE));
        v.z = __uint_as_float(f2tf32(v.z * QSCALE));
        v.w = __uint_as_float(f2tf32(v.w * QSCALE));
        *(float4*)(Qs + r * 68 + dq * 4) = v;
    }
    __syncthreads();

    // Hoist Q fragments (loop-invariant across key tiles)
    uint32_t qa[8][4];
#pragma unroll
    for (int kc = 0; kc < 8; kc++) {
        const float* qr0 = Qs + (w * 16 + tr) * 68 + kc * 8 + tc;
        const float* qr1 = qr0 + 8 * 68;
        qa[kc][0] = __float_as_uint(qr0[0]);
        qa[kc][1] = __float_as_uint(qr1[0]);
        qa[kc][2] = __float_as_uint(qr0[4]);
        qa[kc][3] = __float_as_uint(qr1[4]);
    }

    float m0 = -CUDART_INF_F, m1 = -CUDART_INF_F, l0 = 0.0f, l1 = 0.0f;
    float o[8][4];
    float s[8][4];
#pragma unroll
    for (int nt = 0; nt < 8; nt++)
#pragma unroll
        for (int j = 0; j < 4; j++) o[nt][j] = 0.0f;

    const int ktm = q0 / 64 + 1;
    for (int kt = 0; kt <= ktm; kt++) {
        const int k0 = kt * 64;
        __syncthreads();
        for (int e = tid; e < 64 * 16; e += 256) {
            int r = e >> 4, dq = e & 15;
            float4 kv = *(const float4*)(Kg + (size_t)(b * SEQ + k0 + r) * HDIM + dq * 4);
            kv.x = __uint_as_float(f2tf32(kv.x));
            kv.y = __uint_as_float(f2tf32(kv.y));
            kv.z = __uint_as_float(f2tf32(kv.z));
            kv.w = __uint_as_float(f2tf32(kv.w));
            *(float4*)(Ks + r * 68 + dq * 4) = kv;
            float4 vv = *(const float4*)(Vg + (size_t)(b * SEQ + k0 + r) * HDIM + dq * 4);
            vv.x = __uint_as_float(f2tf32(vv.x));
            vv.y = __uint_as_float(f2tf32(vv.y));
            vv.z = __uint_as_float(f2tf32(vv.z));
            vv.w = __uint_as_float(f2tf32(vv.w));
            *(float4*)(Vs + r * 72 + dq * 4) = vv;
        }
        __syncthreads();

        if (k0 > qw0 + 15) continue;   // warp-uniform; still hits top syncs

        // ---- S = Q K^T (single-pass tf32, log2 domain) ----
#pragma unroll
        for (int nt = 0; nt < 8; nt++)
#pragma unroll
            for (int j = 0; j < 4; j++) s[nt][j] = 0.0f;

#pragma unroll
        for (int kc = 0; kc < 8; kc++) {
#pragma unroll
            for (int nt = 0; nt < 8; nt++) {
                const float* kr = Ks + (nt * 8 + tr) * 68 + kc * 8 + tc;
                uint32_t bk[2];
                bk[0] = __float_as_uint(kr[0]);
                bk[1] = __float_as_uint(kr[4]);
                mma_tf32(s[nt], qa[kc], bk);
            }
        }

        // ---- causal mask (only the diagonal-crossing tile) ----
        if (k0 + 63 > qw0) {
#pragma unroll
            for (int nt = 0; nt < 8; nt++) {
                int key0 = k0 + nt * 8 + 2 * tc;
                int r0 = qw0 + tr, r1 = r0 + 8;
                if (key0 > r0)     s[nt][0] = -CUDART_INF_F;
                if (key0 + 1 > r0) s[nt][1] = -CUDART_INF_F;
                if (key0 > r1)     s[nt][2] = -CUDART_INF_F;
                if (key0 + 1 > r1) s[nt][3] = -CUDART_INF_F;
            }
        }

        // ---- online softmax (log2 domain, FMA-pipe ex2) ----
        float mx0 = -CUDART_INF_F, mx1 = -CUDART_INF_F;
#pragma unroll
        for (int nt = 0; nt < 8; nt++) {
            mx0 = fmaxf(mx0, fmaxf(s[nt][0], s[nt][1]));
            mx1 = fmaxf(mx1, fmaxf(s[nt][2], s[nt][3]));
        }
        mx0 = fmaxf(mx0, __shfl_xor_sync(0xffffffffu, mx0, 1));
        mx0 = fmaxf(mx0, __shfl_xor_sync(0xffffffffu, mx0, 2));
        mx1 = fmaxf(mx1, __shfl_xor_sync(0xffffffffu, mx1, 1));
        mx1 = fmaxf(mx1, __shfl_xor_sync(0xffffffffu, mx1, 2));

        float mn0 = fmaxf(m0, mx0), mn1 = fmaxf(m1, mx1);
        float c0 = ex2_fast(m0 - mn0), c1 = ex2_fast(m1 - mn1);
        m0 = mn0; m1 = mn1;

        float ls0 = 0.0f, ls1 = 0.0f;
#pragma unroll
        for (int nt = 0; nt < 8; nt++) {
            float p0 = ex2_fast(s[nt][0] - mn0);
            float p1 = ex2_fast(s[nt][1] - mn0);
            float p2 = ex2_fast(s[nt][2] - mn1);
            float p3 = ex2_fast(s[nt][3] - mn1);
            ls0 += p0 + p1;
            ls1 += p2 + p3;
            s[nt][0] = __uint_as_float(f2tf32(p0));
            s[nt][1] = __uint_as_float(f2tf32(p1));
            s[nt][2] = __uint_as_float(f2tf32(p2));
            s[nt][3] = __uint_as_float(f2tf32(p3));
        }
        ls0 += __shfl_xor_sync(0xffffffffu, ls0, 1);
        ls0 += __shfl_xor_sync(0xffffffffu, ls0, 2);
        ls1 += __shfl_xor_sync(0xffffffffu, ls1, 1);
        ls1 += __shfl_xor_sync(0xffffffffu, ls1, 2);
        l0 = l0 * c0 + ls0;
        l1 = l1 * c1 + ls1;

#pragma unroll
        for (int nt = 0; nt < 8; nt++) {
            o[nt][0] *= c0; o[nt][1] *= c0;
            o[nt][2] *= c1; o[nt][3] *= c1;
        }

        // ---- O += P V (single-pass tf32); P C-frag -> A-frag via shuffles ----
        const int src  = 4 * tr + (tc >> 1);
        const int src2 = src + 2;
        const bool odd = tc & 1;
#pragma unroll
        for (int kc = 0; kc < 8; kc++) {
            float u0 = __shfl_sync(0xffffffffu, s[kc][0], src);
            float u1 = __shfl_sync(0xffffffffu, s[kc][1], src);
            float v0 = __shfl_sync(0xffffffffu, s[kc][0], src2);
            float v1 = __shfl_sync(0xffffffffu, s[kc][1], src2);
            float w0 = __shfl_sync(0xffffffffu, s[kc][2], src);
            float w1 = __shfl_sync(0xffffffffu, s[kc][3], src);
            float x0 = __shfl_sync(0xffffffffu, s[kc][2], src2);
            float x1 = __shfl_sync(0xffffffffu, s[kc][3], src2);
            uint32_t a[4];
            a[0] = __float_as_uint(odd ? u1 : u0);
            a[1] = __float_as_uint(odd ? w1 : w0);
            a[2] = __float_as_uint(odd ? v1 : v0);
            a[3] = __float_as_uint(odd ? x1 : x0);
#pragma unroll
            for (int nt = 0; nt < 8; nt++) {
                uint32_t bv[2];
                bv[0] = __float_as_uint(Vs[(kc * 8 + tc) * 72 + nt * 8 + tr]);
                bv[1] = __float_as_uint(Vs[(kc * 8 + tc + 4) * 72 + nt * 8 + tr]);
                mma_tf32(o[nt], a, bv);
            }
        }
    }

    // ---- epilogue ----
    const float inv0 = 1.0f / l0, inv1 = 1.0f / l1;
    const size_t gr0 = (size_t)(b * SEQ + qw0 + tr) * EMB + h * HDIM;
    const size_t gr1 = gr0 + 8 * EMB;
#pragma unroll
    for (int nt = 0; nt < 8; nt++) {
        int col = nt * 8 + 2 * tc;
        *(float2*)(out + gr0 + col) = make_float2(o[nt][0] * inv0, o[nt][1] * inv0);
        *(float2*)(out + gr1 + col) = make_float2(o[nt][2] * inv1, o[nt][3] * inv1);
    }
}

// ---------------------------------------------------------------------------
// Launch
// ---------------------------------------------------------------------------
extern "C" void kernel_launch(void* const* d_in, const int* in_sizes, int n_in,
                              void* d_out, int out_size)
{
    const float* X  = (const float*)d_in[0];
    const float* Wq = (const float*)d_in[1];
    const float* Wk = (const float*)d_in[2];
    const float* Wv = (const float*)d_in[3];
    float* out = (float*)d_out;

    float *Qbuf, *Kbuf, *Vbuf;
    cudaGetSymbolAddress((void**)&Qbuf, g_Q);
    cudaGetSymbolAddress((void**)&Kbuf, g_K);
    cudaGetSymbolAddress((void**)&Vbuf, g_V);

    {
        dim3 blk(256);
        dim3 gq(EMB / 128, ROWS / 128, 1);   // (8, 32, 1)
        proj_mma<128, 4><<<gq, blk>>>(X, Wq, Qbuf, Wq, Qbuf, EMB, EMB);
        dim3 gkv(1, ROWS / 128, 2);          // K and V in one launch
        proj_mma<64, 2><<<gkv, blk>>>(X, Wk, Kbuf, Wv, Vbuf, HDIM, EMB);
    }

    {
        cudaFuncSetAttribute(flash_mqa, cudaFuncAttributeMaxDynamicSharedMemorySize, FLASH_SMEM);
        dim3 blk(256);
        dim3 grid(SEQ / QT, HEADS, BATCH);   // (16, 16, 2)
        flash_mqa<<<grid, blk, FLASH_SMEM>>>(Qbuf, Kbuf, Vbuf, out);
    }
}